// round 7
// baseline (speedup 1.0000x reference)
#include <cuda_runtime.h>
#include <stdint.h>

// Hash constants: ((c+1) * PIS[c]) for c = 0..7 (exact 64-bit products).
// tidx = (idx ^ PP[c]) & (TABLE_SIZE-1); valid since idx >= 0, TABLE_SIZE = 2^19.
__constant__ unsigned long long c_pp[8] = {
    774363409ull, 5308871522ull, 2416379583ull, 400000028ull,
    1671816955ull, 8006180478ull, 5140543849ull, 17074907144ull
};

#define TABLE_MASK 0x7FFFFull
#define NRED 32
#define FULLM 0xffffffffu

static __device__ int g_partial[NRED];

// ---------------------------------------------------------------------------
// Kernel 1: per-block max over depth -> g_partial[blockIdx]
// ---------------------------------------------------------------------------
__global__ void depth_reduce_kernel(const int* __restrict__ depth, int n) {
    int m = 0;
    for (int i = blockIdx.x * blockDim.x + threadIdx.x; i < n;
         i += gridDim.x * blockDim.x)
        m = max(m, depth[i]);
    #pragma unroll
    for (int s = 16; s > 0; s >>= 1)
        m = max(m, __shfl_xor_sync(FULLM, m, s));
    __shared__ int sm[32];
    int w = threadIdx.x >> 5;
    if ((threadIdx.x & 31) == 0) sm[w] = m;
    __syncthreads();
    if (threadIdx.x == 0) {
        int nw = (blockDim.x + 31) >> 5;
        int mm = sm[0];
        for (int i = 1; i < nw; i++) mm = max(mm, sm[i]);
        g_partial[blockIdx.x] = mm;
    }
}

// ---------------------------------------------------------------------------
// Kernel 2: main encoding. Block = one ray (256 threads). Warp w = level l.
// Key structure: the ONLY block-wide barrier happens early (protects s_inp +
// s_activeL, produced by cheap coalesced loads). The feature gather -> STS ->
// LDS path is per-warp private (sfeat[w] touched only by warp w), ordered by
// __syncwarp, so no warp waits on another warp's scattered gather latency.
// Output uses streaming stores (__stcs) so the 256MB write stream does not
// evict the L2-resident 32MB emb table.
// ---------------------------------------------------------------------------
__global__ void __launch_bounds__(256, 8) nbvh_main_kernel(
    const float* __restrict__ inp,          // [R,16,3]
    const int*   __restrict__ history,      // [R,64]
    const float* __restrict__ nodes_min,    // [N,3]
    const float* __restrict__ nodes_extent, // [N,3]
    const float* __restrict__ emb,          // [524288,16]
    float* __restrict__ out)                // [R, 8*16*16]
{
    __shared__ float4 sfeat[8][32];   // [warp][corner*4 + dim_group]
    __shared__ float  s_inp[48];      // this ray's 16x3 coords
    __shared__ int    s_activeL;

    const int tid  = threadIdx.x;
    const int w    = tid >> 5;       // level l
    const int lane = tid & 31;
    const int r    = blockIdx.x;

    const int idx = history[r * 64 + w];

    // Issue the scattered gather as early as possible (in-flight across the
    // barrier). lane -> (corner = lane>>2, float4 sub = lane&3).
    const int c_   = lane >> 2;
    const int sub_ = lane & 3;
    unsigned tix =
        (unsigned)(((unsigned long long)(unsigned)idx ^ c_pp[c_]) & TABLE_MASK);
    const float4 fg =
        reinterpret_cast<const float4*>(emb)[(size_t)tix * 4 + sub_];

    // Node box (uniform within warp -> 1 wavefront per load)
    const float pmx = nodes_min[(size_t)idx * 3 + 0];
    const float pmy = nodes_min[(size_t)idx * 3 + 1];
    const float pmz = nodes_min[(size_t)idx * 3 + 2];
    const float rex = __fdividef(1.0f, nodes_extent[(size_t)idx * 3 + 0]);
    const float rey = __fdividef(1.0f, nodes_extent[(size_t)idx * 3 + 1]);
    const float rez = __fdividef(1.0f, nodes_extent[(size_t)idx * 3 + 2]);

    // warp 0: parallel reduce of the 32 partials
    if (tid < 32) {
        int m = g_partial[tid];
        #pragma unroll
        for (int s = 16; s > 0; s >>= 1)
            m = max(m, __shfl_xor_sync(FULLM, m, s));
        if (tid == 0) s_activeL = (m < 8) ? m : 8;
    }
    // warp 1: stage this ray's 48 coords (12 float4, coalesced)
    if (tid >= 32 && tid < 44) {
        reinterpret_cast<float4*>(s_inp)[tid - 32] =
            reinterpret_cast<const float4*>(inp + (size_t)r * 48)[tid - 32];
    }

    // EARLY block barrier: only s_inp/s_activeL cross warps. Gathers are
    // still in flight here; no warp waits on another's gather.
    __syncthreads();

    const float act  = (w < s_activeL) ? 1.0f : 0.0f;
    const int   p_lo = lane >> 2;     // points p_lo and p_lo+8
    const int   dsub = lane & 3;      // float4 dim group

    // Factorized weights: P[half][4] xy-products, Z[half][2] z-terms (act in)
    float P[2][4], Z[2][2];
    #pragma unroll
    for (int half = 0; half < 2; half++) {
        const int p = p_lo + 8 * half;
        float x = fminf(fmaxf((s_inp[p * 3 + 0] - pmx) * rex, 0.0f), 1.0f);
        float y = fminf(fmaxf((s_inp[p * 3 + 1] - pmy) * rey, 0.0f), 1.0f);
        float z = fminf(fmaxf((s_inp[p * 3 + 2] - pmz) * rez, 0.0f), 1.0f);
        const float ix = 1.0f - x, iy = 1.0f - y;
        P[half][0] = ix * iy;  P[half][1] = x * iy;
        P[half][2] = ix * y;   P[half][3] = x * y;
        Z[half][0] = (1.0f - z) * act;
        Z[half][1] = z * act;
    }

    // Per-warp private staging: STS waits only on THIS warp's gather.
    sfeat[w][lane] = fg;
    __syncwarp();

    float4 alo = make_float4(0.f, 0.f, 0.f, 0.f);
    float4 ahi = make_float4(0.f, 0.f, 0.f, 0.f);

    // corner -> (P index, Z index):
    //   c:  0  1  2  3  4  5  6  7
    //  pi:  0  1  2  0  1  2  3  3
    //  zi:  0  0  0  1  1  1  0  1
    const int pi_[8] = {0, 1, 2, 0, 1, 2, 3, 3};
    const int zi_[8] = {0, 0, 0, 1, 1, 1, 0, 1};
    #pragma unroll
    for (int c = 0; c < 8; c++) {
        const float4 f  = sfeat[w][c * 4 + dsub];   // broadcast LDS.128
        const float  wl = P[0][pi_[c]] * Z[0][zi_[c]];
        const float  wh = P[1][pi_[c]] * Z[1][zi_[c]];
        alo.x = fmaf(wl, f.x, alo.x);
        alo.y = fmaf(wl, f.y, alo.y);
        alo.z = fmaf(wl, f.z, alo.z);
        alo.w = fmaf(wl, f.w, alo.w);
        ahi.x = fmaf(wh, f.x, ahi.x);
        ahi.y = fmaf(wh, f.y, ahi.y);
        ahi.z = fmaf(wh, f.z, ahi.z);
        ahi.w = fmaf(wh, f.w, ahi.w);
    }

    // Output tile for (r, l): 64 float4; two contiguous 512B warp stores,
    // streaming (evict-first) so writes don't thrash emb out of L2.
    float4* o = reinterpret_cast<float4*>(out) + ((size_t)r * 8 + w) * 64;
    __stcs(o + lane, alo);
    __stcs(o + 32 + lane, ahi);
}

// ---------------------------------------------------------------------------
extern "C" void kernel_launch(void* const* d_in, const int* in_sizes, int n_in,
                              void* d_out, int out_size) {
    const float* inp     = (const float*)d_in[0];
    const int*   history = (const int*)d_in[1];
    const int*   depth   = (const int*)d_in[2];
    const float* nmin    = (const float*)d_in[3];
    const float* next    = (const float*)d_in[4];
    const float* emb     = (const float*)d_in[5];
    float*       out     = (float*)d_out;

    const int R = in_sizes[2];   // number of rays (= depth element count)

    depth_reduce_kernel<<<NRED, 256>>>(depth, R);
    nbvh_main_kernel<<<R, 256>>>(inp, history, nmin, next, emb, out);
}

// round 8
// speedup vs baseline: 1.6434x; 1.6434x over previous
#include <cuda_runtime.h>
#include <stdint.h>

// Hash constants: ((c+1) * PIS[c]) for c = 0..7 (exact 64-bit products).
// tidx = (idx ^ PP[c]) & (TABLE_SIZE-1); valid since idx >= 0, TABLE_SIZE = 2^19.
__constant__ unsigned long long c_pp[8] = {
    774363409ull, 5308871522ull, 2416379583ull, 400000028ull,
    1671816955ull, 8006180478ull, 5140543849ull, 17074907144ull
};

#define TABLE_MASK 0x7FFFFull
#define NRED 32
#define FULLM 0xffffffffu
#define NRAY 4

static __device__ int g_partial[NRED];

// ---------------------------------------------------------------------------
// Kernel 1: per-block max over depth -> g_partial[blockIdx]
// ---------------------------------------------------------------------------
__global__ void depth_reduce_kernel(const int* __restrict__ depth, int n) {
    int m = 0;
    for (int i = blockIdx.x * blockDim.x + threadIdx.x; i < n;
         i += gridDim.x * blockDim.x)
        m = max(m, depth[i]);
    #pragma unroll
    for (int s = 16; s > 0; s >>= 1)
        m = max(m, __shfl_xor_sync(FULLM, m, s));
    __shared__ int sm[32];
    int w = threadIdx.x >> 5;
    if ((threadIdx.x & 31) == 0) sm[w] = m;
    __syncthreads();
    if (threadIdx.x == 0) {
        int nw = (blockDim.x + 31) >> 5;
        int mm = sm[0];
        for (int i = 1; i < nw; i++) mm = max(mm, sm[i]);
        g_partial[blockIdx.x] = mm;
    }
}

// ---------------------------------------------------------------------------
// Kernel 2: main encoding, software-pipelined over NRAY rays per block.
// Warp w = level l. Per iteration j: prefetch ray j+1's emb gather + node
// box (registers), then compute ray j. The scattered-gather latency of ray
// j+1 is hidden behind ray j's weight/FMA/store work. sfeat double-buffered
// by j-parity so one __syncwarp per iteration suffices (no cross-warp sync
// after the single early __syncthreads).
// ---------------------------------------------------------------------------
__global__ void __launch_bounds__(256, 5) nbvh_main_kernel(
    const float* __restrict__ inp,          // [R,16,3]
    const int*   __restrict__ history,      // [R,64]
    const float* __restrict__ nodes_min,    // [N,3]
    const float* __restrict__ nodes_extent, // [N,3]
    const float* __restrict__ emb,          // [524288,16]
    float* __restrict__ out,                // [R, 8*16*16]
    int R)
{
    __shared__ float4 sfeat[8][2][32];   // [warp][parity][corner*4+dim_group]
    __shared__ float  s_inp[NRAY * 48];
    __shared__ int    s_activeL;

    const int tid  = threadIdx.x;
    const int w    = tid >> 5;       // level l
    const int lane = tid & 31;
    const int r0   = blockIdx.x * NRAY;

    // Stage NRAY rays' coords (48 float4, coalesced, warps 0+1)
    if (tid < NRAY * 12) {
        const int gi = blockIdx.x * (NRAY * 12) + tid;
        float4 v = make_float4(0.f, 0.f, 0.f, 0.f);
        if (gi < R * 12)
            v = reinterpret_cast<const float4*>(inp)[gi];
        reinterpret_cast<float4*>(s_inp)[tid] = v;
    }
    // warp 7: reduce the 32 depth partials
    if (w == 7) {
        int m = g_partial[lane];
        #pragma unroll
        for (int s = 16; s > 0; s >>= 1)
            m = max(m, __shfl_xor_sync(FULLM, m, s));
        if (lane == 0) s_activeL = (m < 8) ? m : 8;
    }

    // All NRAY history indices up-front (MLP=4)
    int idxs[NRAY];
    #pragma unroll
    for (int j = 0; j < NRAY; j++) {
        int rj = r0 + j; if (rj >= R) rj = R - 1;
        idxs[j] = history[rj * 64 + w];
    }

    const int c_   = lane >> 2;      // corner for gather
    const int sub_ = lane & 3;       // float4 sub for gather
    const float4* e4 = reinterpret_cast<const float4*>(emb);

    // Prologue: stage-0 gather + node box
    float4 fg;
    float  bx0, bx1, bx2, br0, br1, br2;
    {
        const unsigned tix = (unsigned)(((unsigned long long)(unsigned)idxs[0]
                                          ^ c_pp[c_]) & TABLE_MASK);
        fg  = e4[(size_t)tix * 4 + sub_];
        bx0 = nodes_min[(size_t)idxs[0] * 3 + 0];
        bx1 = nodes_min[(size_t)idxs[0] * 3 + 1];
        bx2 = nodes_min[(size_t)idxs[0] * 3 + 2];
        br0 = __fdividef(1.0f, nodes_extent[(size_t)idxs[0] * 3 + 0]);
        br1 = __fdividef(1.0f, nodes_extent[(size_t)idxs[0] * 3 + 1]);
        br2 = __fdividef(1.0f, nodes_extent[(size_t)idxs[0] * 3 + 2]);
    }

    __syncthreads();   // s_inp + s_activeL visible

    const float act  = (w < s_activeL) ? 1.0f : 0.0f;
    const int   p_lo = lane >> 2;     // points p_lo and p_lo+8
    const int   dsub = lane & 3;      // float4 dim group

    const int pi_[8] = {0, 1, 2, 0, 1, 2, 3, 3};
    const int zi_[8] = {0, 0, 0, 1, 1, 1, 0, 1};

    #pragma unroll
    for (int j = 0; j < NRAY; j++) {
        // ---- prefetch stage j+1 (in flight during compute of stage j) ----
        float4 fg_n = fg;
        float  nx0 = bx0, nx1 = bx1, nx2 = bx2;
        float  nr0 = br0, nr1 = br1, nr2 = br2;
        if (j + 1 < NRAY) {
            const int in_ = idxs[j + 1];
            const unsigned tixn = (unsigned)(((unsigned long long)(unsigned)in_
                                              ^ c_pp[c_]) & TABLE_MASK);
            fg_n = e4[(size_t)tixn * 4 + sub_];
            nx0 = nodes_min[(size_t)in_ * 3 + 0];
            nx1 = nodes_min[(size_t)in_ * 3 + 1];
            nx2 = nodes_min[(size_t)in_ * 3 + 2];
            nr0 = __fdividef(1.0f, nodes_extent[(size_t)in_ * 3 + 0]);
            nr1 = __fdividef(1.0f, nodes_extent[(size_t)in_ * 3 + 1]);
            nr2 = __fdividef(1.0f, nodes_extent[(size_t)in_ * 3 + 2]);
        }

        // ---- compute stage j ----
        const float* ci = s_inp + j * 48;
        float P[2][4], Z[2][2];
        #pragma unroll
        for (int half = 0; half < 2; half++) {
            const int p = p_lo + 8 * half;
            float x = fminf(fmaxf((ci[p * 3 + 0] - bx0) * br0, 0.0f), 1.0f);
            float y = fminf(fmaxf((ci[p * 3 + 1] - bx1) * br1, 0.0f), 1.0f);
            float z = fminf(fmaxf((ci[p * 3 + 2] - bx2) * br2, 0.0f), 1.0f);
            const float ix = 1.0f - x, iy = 1.0f - y;
            P[half][0] = ix * iy;  P[half][1] = x * iy;
            P[half][2] = ix * y;   P[half][3] = x * y;
            Z[half][0] = (1.0f - z) * act;
            Z[half][1] = z * act;
        }

        sfeat[w][j & 1][lane] = fg;   // waits only on THIS warp's stage-j gather
        __syncwarp();

        float4 alo = make_float4(0.f, 0.f, 0.f, 0.f);
        float4 ahi = make_float4(0.f, 0.f, 0.f, 0.f);
        #pragma unroll
        for (int c = 0; c < 8; c++) {
            const float4 f  = sfeat[w][j & 1][c * 4 + dsub];
            const float  wl = P[0][pi_[c]] * Z[0][zi_[c]];
            const float  wh = P[1][pi_[c]] * Z[1][zi_[c]];
            alo.x = fmaf(wl, f.x, alo.x);
            alo.y = fmaf(wl, f.y, alo.y);
            alo.z = fmaf(wl, f.z, alo.z);
            alo.w = fmaf(wl, f.w, alo.w);
            ahi.x = fmaf(wh, f.x, ahi.x);
            ahi.y = fmaf(wh, f.y, ahi.y);
            ahi.z = fmaf(wh, f.z, ahi.z);
            ahi.w = fmaf(wh, f.w, ahi.w);
        }

        if (r0 + j < R) {
            float4* o = reinterpret_cast<float4*>(out)
                        + ((size_t)(r0 + j) * 8 + w) * 64;
            o[lane]      = alo;
            o[32 + lane] = ahi;
        }

        // stop the unroller from hoisting all gathers into one batch
        asm volatile("" ::: "memory");

        fg = fg_n;
        bx0 = nx0; bx1 = nx1; bx2 = nx2;
        br0 = nr0; br1 = nr1; br2 = nr2;
    }
}

// ---------------------------------------------------------------------------
extern "C" void kernel_launch(void* const* d_in, const int* in_sizes, int n_in,
                              void* d_out, int out_size) {
    const float* inp     = (const float*)d_in[0];
    const int*   history = (const int*)d_in[1];
    const int*   depth   = (const int*)d_in[2];
    const float* nmin    = (const float*)d_in[3];
    const float* next    = (const float*)d_in[4];
    const float* emb     = (const float*)d_in[5];
    float*       out     = (float*)d_out;

    const int R = in_sizes[2];   // number of rays (= depth element count)

    depth_reduce_kernel<<<NRED, 256>>>(depth, R);
    nbvh_main_kernel<<<(R + NRAY - 1) / NRAY, 256>>>(
        inp, history, nmin, next, emb, out, R);
}

// round 9
// speedup vs baseline: 1.6978x; 1.0331x over previous
#include <cuda_runtime.h>
#include <stdint.h>

// Hash constants: ((c+1) * PIS[c]) for c = 0..7 (exact 64-bit products).
// tidx = (idx ^ PP[c]) & (TABLE_SIZE-1); valid since idx >= 0, TABLE_SIZE = 2^19.
__constant__ unsigned long long c_pp[8] = {
    774363409ull, 5308871522ull, 2416379583ull, 400000028ull,
    1671816955ull, 8006180478ull, 5140543849ull, 17074907144ull
};

#define TABLE_MASK 0x7FFFFull
#define NRED 32
#define FULLM 0xffffffffu
#define NRAY 8

static __device__ int g_partial[NRED];
static __device__ int g_activeL;

// ---------------------------------------------------------------------------
// Kernel 1: per-block max over depth; block 0 of a second pass folds partials.
// Two tiny launches avoided by: each block writes its partial, then the last
// block to finish (atomic ticket) reduces all partials into g_activeL.
// ---------------------------------------------------------------------------
static __device__ unsigned g_ticket;

__global__ void depth_reduce_kernel(const int* __restrict__ depth, int n) {
    int m = 0;
    for (int i = blockIdx.x * blockDim.x + threadIdx.x; i < n;
         i += gridDim.x * blockDim.x)
        m = max(m, depth[i]);
    #pragma unroll
    for (int s = 16; s > 0; s >>= 1)
        m = max(m, __shfl_xor_sync(FULLM, m, s));
    __shared__ int sm[32];
    __shared__ bool last;
    int w = threadIdx.x >> 5;
    if ((threadIdx.x & 31) == 0) sm[w] = m;
    __syncthreads();
    if (threadIdx.x == 0) {
        int nw = (blockDim.x + 31) >> 5;
        int mm = sm[0];
        for (int i = 1; i < nw; i++) mm = max(mm, sm[i]);
        g_partial[blockIdx.x] = mm;
        __threadfence();
        unsigned t = atomicAdd(&g_ticket, 1u);
        last = (t == (unsigned)(gridDim.x - 1));
    }
    __syncthreads();
    if (last && threadIdx.x < 32) {
        int mm = g_partial[threadIdx.x];
        #pragma unroll
        for (int s = 16; s > 0; s >>= 1)
            mm = max(mm, __shfl_xor_sync(FULLM, mm, s));
        if (threadIdx.x == 0) {
            g_activeL = (mm < 8) ? mm : 8;
            g_ticket = 0;                 // reset for next (graph replay) call
        }
    }
}

// ---------------------------------------------------------------------------
// Kernel 2: main encoding, software-pipelined over NRAY=8 rays per block.
// Warp w = level l. Per iteration j: prefetch ray j+1's emb gather + node
// box (registers), then compute ray j. sfeat double-buffered by j-parity,
// one __syncwarp per iteration; single early __syncthreads for s_inp.
// ---------------------------------------------------------------------------
__global__ void __launch_bounds__(256, 5) nbvh_main_kernel(
    const float* __restrict__ inp,          // [R,16,3]
    const int*   __restrict__ history,      // [R,64]
    const float* __restrict__ nodes_min,    // [N,3]
    const float* __restrict__ nodes_extent, // [N,3]
    const float* __restrict__ emb,          // [524288,16]
    float* __restrict__ out,                // [R, 8*16*16]
    int R)
{
    __shared__ float4 sfeat[8][2][32];   // [warp][parity][corner*4+dim_group]
    __shared__ float  s_inp[NRAY * 48];

    const int tid  = threadIdx.x;
    const int w    = tid >> 5;       // level l
    const int lane = tid & 31;
    const int r0   = blockIdx.x * NRAY;

    // Stage NRAY rays' coords (96 float4, coalesced)
    if (tid < NRAY * 12) {
        const int gi = blockIdx.x * (NRAY * 12) + tid;
        float4 v = make_float4(0.f, 0.f, 0.f, 0.f);
        if (gi < R * 12)
            v = reinterpret_cast<const float4*>(inp)[gi];
        reinterpret_cast<float4*>(s_inp)[tid] = v;
    }

    const int activeL = g_activeL;     // uniform scalar, L2-resident
    const float act   = (w < activeL) ? 1.0f : 0.0f;

    // All NRAY history indices up-front (MLP=8)
    int idxs[NRAY];
    #pragma unroll
    for (int j = 0; j < NRAY; j++) {
        int rj = r0 + j; if (rj >= R) rj = R - 1;
        idxs[j] = history[rj * 64 + w];
    }

    const int c_   = lane >> 2;      // corner for gather
    const int sub_ = lane & 3;       // float4 sub for gather
    const float4* e4 = reinterpret_cast<const float4*>(emb);

    // Prologue: stage-0 gather + node box
    float4 fg;
    float  bx0, bx1, bx2, br0, br1, br2;
    {
        const unsigned tix = (unsigned)(((unsigned long long)(unsigned)idxs[0]
                                          ^ c_pp[c_]) & TABLE_MASK);
        fg  = e4[(size_t)tix * 4 + sub_];
        bx0 = nodes_min[(size_t)idxs[0] * 3 + 0];
        bx1 = nodes_min[(size_t)idxs[0] * 3 + 1];
        bx2 = nodes_min[(size_t)idxs[0] * 3 + 2];
        br0 = __fdividef(1.0f, nodes_extent[(size_t)idxs[0] * 3 + 0]);
        br1 = __fdividef(1.0f, nodes_extent[(size_t)idxs[0] * 3 + 1]);
        br2 = __fdividef(1.0f, nodes_extent[(size_t)idxs[0] * 3 + 2]);
    }

    __syncthreads();   // s_inp visible

    const int p_lo = lane >> 2;     // points p_lo and p_lo+8
    const int dsub = lane & 3;      // float4 dim group
    const bool full = (r0 + NRAY <= R);

    const int pi_[8] = {0, 1, 2, 0, 1, 2, 3, 3};
    const int zi_[8] = {0, 0, 0, 1, 1, 1, 0, 1};

    #pragma unroll
    for (int j = 0; j < NRAY; j++) {
        // ---- prefetch stage j+1 (in flight during compute of stage j) ----
        float4 fg_n = fg;
        float  nx0 = bx0, nx1 = bx1, nx2 = bx2;
        float  nr0 = br0, nr1 = br1, nr2 = br2;
        if (j + 1 < NRAY) {
            const int in_ = idxs[j + 1];
            const unsigned tixn = (unsigned)(((unsigned long long)(unsigned)in_
                                              ^ c_pp[c_]) & TABLE_MASK);
            fg_n = e4[(size_t)tixn * 4 + sub_];
            nx0 = nodes_min[(size_t)in_ * 3 + 0];
            nx1 = nodes_min[(size_t)in_ * 3 + 1];
            nx2 = nodes_min[(size_t)in_ * 3 + 2];
            nr0 = __fdividef(1.0f, nodes_extent[(size_t)in_ * 3 + 0]);
            nr1 = __fdividef(1.0f, nodes_extent[(size_t)in_ * 3 + 1]);
            nr2 = __fdividef(1.0f, nodes_extent[(size_t)in_ * 3 + 2]);
        }

        // ---- compute stage j ----
        const float* ci = s_inp + j * 48;
        float P[2][4], Z[2][2];
        #pragma unroll
        for (int half = 0; half < 2; half++) {
            const int p = p_lo + 8 * half;
            float x = fminf(fmaxf((ci[p * 3 + 0] - bx0) * br0, 0.0f), 1.0f);
            float y = fminf(fmaxf((ci[p * 3 + 1] - bx1) * br1, 0.0f), 1.0f);
            float z = fminf(fmaxf((ci[p * 3 + 2] - bx2) * br2, 0.0f), 1.0f);
            const float ix = 1.0f - x, iy = 1.0f - y;
            P[half][0] = ix * iy;  P[half][1] = x * iy;
            P[half][2] = ix * y;   P[half][3] = x * y;
            Z[half][0] = (1.0f - z) * act;
            Z[half][1] = z * act;
        }

        sfeat[w][j & 1][lane] = fg;   // waits only on THIS warp's stage-j gather
        __syncwarp();

        float4 alo = make_float4(0.f, 0.f, 0.f, 0.f);
        float4 ahi = make_float4(0.f, 0.f, 0.f, 0.f);
        #pragma unroll
        for (int c = 0; c < 8; c++) {
            const float4 f  = sfeat[w][j & 1][c * 4 + dsub];
            const float  wl = P[0][pi_[c]] * Z[0][zi_[c]];
            const float  wh = P[1][pi_[c]] * Z[1][zi_[c]];
            alo.x = fmaf(wl, f.x, alo.x);
            alo.y = fmaf(wl, f.y, alo.y);
            alo.z = fmaf(wl, f.z, alo.z);
            alo.w = fmaf(wl, f.w, alo.w);
            ahi.x = fmaf(wh, f.x, ahi.x);
            ahi.y = fmaf(wh, f.y, ahi.y);
            ahi.z = fmaf(wh, f.z, ahi.z);
            ahi.w = fmaf(wh, f.w, ahi.w);
        }

        if (full || (r0 + j < R)) {
            float4* o = reinterpret_cast<float4*>(out)
                        + ((size_t)(r0 + j) * 8 + w) * 64;
            o[lane]      = alo;
            o[32 + lane] = ahi;
        }

        // stop the unroller from hoisting all gathers into one batch
        asm volatile("" ::: "memory");

        fg = fg_n;
        bx0 = nx0; bx1 = nx1; bx2 = nx2;
        br0 = nr0; br1 = nr1; br2 = nr2;
    }
}

// ---------------------------------------------------------------------------
extern "C" void kernel_launch(void* const* d_in, const int* in_sizes, int n_in,
                              void* d_out, int out_size) {
    const float* inp     = (const float*)d_in[0];
    const int*   history = (const int*)d_in[1];
    const int*   depth   = (const int*)d_in[2];
    const float* nmin    = (const float*)d_in[3];
    const float* next    = (const float*)d_in[4];
    const float* emb     = (const float*)d_in[5];
    float*       out     = (float*)d_out;

    const int R = in_sizes[2];   // number of rays (= depth element count)

    depth_reduce_kernel<<<NRED, 256>>>(depth, R);
    nbvh_main_kernel<<<(R + NRAY - 1) / NRAY, 256>>>(
        inp, history, nmin, next, emb, out, R);
}

// round 10
// speedup vs baseline: 1.7309x; 1.0195x over previous
#include <cuda_runtime.h>
#include <stdint.h>

// Hash constants: ((c+1) * PIS[c]) for c = 0..7 (exact 64-bit products).
// tidx = (idx ^ PP[c]) & (TABLE_SIZE-1); valid since idx >= 0, TABLE_SIZE = 2^19.
__constant__ unsigned long long c_pp[8] = {
    774363409ull, 5308871522ull, 2416379583ull, 400000028ull,
    1671816955ull, 8006180478ull, 5140543849ull, 17074907144ull
};

#define TABLE_MASK 0x7FFFFull
#define NRED 32
#define FULLM 0xffffffffu
#define NRAY 8

static __device__ int g_partial[NRED];
static __device__ int g_activeL;
static __device__ unsigned g_ticket;

#define CP_ASYNC16(dst_smem, src_gmem)                                   \
    asm volatile("cp.async.cg.shared.global [%0], [%1], 16;"             \
                 :: "r"(dst_smem), "l"(src_gmem))
#define CP_COMMIT() asm volatile("cp.async.commit_group;" ::: "memory")
template <int N>
__device__ __forceinline__ void cp_wait() {
    asm volatile("cp.async.wait_group %0;" :: "n"(N) : "memory");
}

// ---------------------------------------------------------------------------
// Kernel 1: grid max over depth -> g_activeL (last block folds partials)
// ---------------------------------------------------------------------------
__global__ void depth_reduce_kernel(const int* __restrict__ depth, int n) {
    int m = 0;
    for (int i = blockIdx.x * blockDim.x + threadIdx.x; i < n;
         i += gridDim.x * blockDim.x)
        m = max(m, depth[i]);
    #pragma unroll
    for (int s = 16; s > 0; s >>= 1)
        m = max(m, __shfl_xor_sync(FULLM, m, s));
    __shared__ int sm[32];
    __shared__ bool last;
    int w = threadIdx.x >> 5;
    if ((threadIdx.x & 31) == 0) sm[w] = m;
    __syncthreads();
    if (threadIdx.x == 0) {
        int nw = (blockDim.x + 31) >> 5;
        int mm = sm[0];
        for (int i = 1; i < nw; i++) mm = max(mm, sm[i]);
        g_partial[blockIdx.x] = mm;
        __threadfence();
        unsigned t = atomicAdd(&g_ticket, 1u);
        last = (t == (unsigned)(gridDim.x - 1));
    }
    __syncthreads();
    if (last && threadIdx.x < 32) {
        int mm = g_partial[threadIdx.x];
        #pragma unroll
        for (int s = 16; s > 0; s >>= 1)
            mm = max(mm, __shfl_xor_sync(FULLM, mm, s));
        if (threadIdx.x == 0) {
            g_activeL = (mm < 8) ? mm : 8;
            g_ticket = 0;                 // reset for graph replay
        }
    }
}

// ---------------------------------------------------------------------------
// Kernel 2: main encoding, NRAY=8 rays/block, warp = level.
// Feature gather via cp.async (LDGSTS) into a 4-slot smem ring, prefetch
// depth 2: at iteration j the gathers for stages j+1 and j+2 are in flight
// while stage j computes. No gather registers, no STS — fewer L1 wavefronts
// and lower register pressure (6 blocks/SM).
// ---------------------------------------------------------------------------
__global__ void __launch_bounds__(256, 6) nbvh_main_kernel(
    const float* __restrict__ inp,          // [R,16,3]
    const int*   __restrict__ history,      // [R,64]
    const float* __restrict__ nodes_min,    // [N,3]
    const float* __restrict__ nodes_extent, // [N,3]
    const float* __restrict__ emb,          // [524288,16]
    float* __restrict__ out,                // [R, 8*16*16]
    int R)
{
    __shared__ float4 sfeat[8][4][32];   // [warp][ring][corner*4+dim_group]
    __shared__ float  s_inp[NRAY * 48];

    const int tid  = threadIdx.x;
    const int w    = tid >> 5;       // level l
    const int lane = tid & 31;
    const int r0   = blockIdx.x * NRAY;

    // Stage NRAY rays' coords (96 float4, coalesced)
    if (tid < NRAY * 12) {
        const int gi = blockIdx.x * (NRAY * 12) + tid;
        float4 v = make_float4(0.f, 0.f, 0.f, 0.f);
        if (gi < R * 12)
            v = reinterpret_cast<const float4*>(inp)[gi];
        reinterpret_cast<float4*>(s_inp)[tid] = v;
    }

    const int activeL = g_activeL;     // uniform scalar
    const float act   = (w < activeL) ? 1.0f : 0.0f;

    // All NRAY history indices up-front (MLP=8)
    int idxs[NRAY];
    #pragma unroll
    for (int j = 0; j < NRAY; j++) {
        int rj = r0 + j; if (rj >= R) rj = R - 1;
        idxs[j] = history[rj * 64 + w];
    }

    const int c_   = lane >> 2;      // corner for gather
    const int sub_ = lane & 3;       // float4 sub for gather
    const float4* e4 = reinterpret_cast<const float4*>(emb);

    // smem address of this lane's gather slot for ring buffer b
    const unsigned smem_lane_base =
        (unsigned)__cvta_generic_to_shared(&sfeat[w][0][lane]);
    // slot stride between ring buffers = 32 * 16 bytes
#define GATHER(stage)                                                        \
    {                                                                        \
        const unsigned tixg =                                                \
            (unsigned)(((unsigned long long)(unsigned)idxs[stage]            \
                        ^ c_pp[c_]) & TABLE_MASK);                           \
        CP_ASYNC16(smem_lane_base + ((stage) & 3) * (32 * 16),               \
                   e4 + (size_t)tixg * 4 + sub_);                            \
        CP_COMMIT();                                                         \
    }

    // Prologue: stages 0 and 1 in flight; stage-0 node box
    GATHER(0);
    GATHER(1);
    float bx0, bx1, bx2, br0, br1, br2;
    {
        bx0 = nodes_min[(size_t)idxs[0] * 3 + 0];
        bx1 = nodes_min[(size_t)idxs[0] * 3 + 1];
        bx2 = nodes_min[(size_t)idxs[0] * 3 + 2];
        br0 = __fdividef(1.0f, nodes_extent[(size_t)idxs[0] * 3 + 0]);
        br1 = __fdividef(1.0f, nodes_extent[(size_t)idxs[0] * 3 + 1]);
        br2 = __fdividef(1.0f, nodes_extent[(size_t)idxs[0] * 3 + 2]);
    }

    __syncthreads();   // s_inp visible

    const int p_lo = lane >> 2;     // points p_lo and p_lo+8
    const int dsub = lane & 3;      // float4 dim group
    const bool full = (r0 + NRAY <= R);

    const int pi_[8] = {0, 1, 2, 0, 1, 2, 3, 3};
    const int zi_[8] = {0, 0, 0, 1, 1, 1, 0, 1};

    #pragma unroll
    for (int j = 0; j < NRAY; j++) {
        // ---- launch stage j+2 gather; prefetch stage j+1 node box ----
        if (j + 2 < NRAY) GATHER(j + 2);
        float nx0 = bx0, nx1 = bx1, nx2 = bx2;
        float nr0 = br0, nr1 = br1, nr2 = br2;
        if (j + 1 < NRAY) {
            const int in_ = idxs[j + 1];
            nx0 = nodes_min[(size_t)in_ * 3 + 0];
            nx1 = nodes_min[(size_t)in_ * 3 + 1];
            nx2 = nodes_min[(size_t)in_ * 3 + 2];
            nr0 = __fdividef(1.0f, nodes_extent[(size_t)in_ * 3 + 0]);
            nr1 = __fdividef(1.0f, nodes_extent[(size_t)in_ * 3 + 1]);
            nr2 = __fdividef(1.0f, nodes_extent[(size_t)in_ * 3 + 2]);
        }

        // ---- weights for stage j ----
        const float* ci = s_inp + j * 48;
        float P[2][4], Z[2][2];
        #pragma unroll
        for (int half = 0; half < 2; half++) {
            const int p = p_lo + 8 * half;
            float x = fminf(fmaxf((ci[p * 3 + 0] - bx0) * br0, 0.0f), 1.0f);
            float y = fminf(fmaxf((ci[p * 3 + 1] - bx1) * br1, 0.0f), 1.0f);
            float z = fminf(fmaxf((ci[p * 3 + 2] - bx2) * br2, 0.0f), 1.0f);
            const float ix = 1.0f - x, iy = 1.0f - y;
            P[half][0] = ix * iy;  P[half][1] = x * iy;
            P[half][2] = ix * y;   P[half][3] = x * y;
            Z[half][0] = (1.0f - z) * act;
            Z[half][1] = z * act;
        }

        // ---- wait for stage j's gather (leave j+1, j+2 in flight) ----
        if (j + 2 < NRAY)      cp_wait<2>();
        else if (j + 1 < NRAY) cp_wait<1>();
        else                   cp_wait<0>();
        __syncwarp();

        float4 alo = make_float4(0.f, 0.f, 0.f, 0.f);
        float4 ahi = make_float4(0.f, 0.f, 0.f, 0.f);
        #pragma unroll
        for (int c = 0; c < 8; c++) {
            const float4 f  = sfeat[w][j & 3][c * 4 + dsub];
            const float  wl = P[0][pi_[c]] * Z[0][zi_[c]];
            const float  wh = P[1][pi_[c]] * Z[1][zi_[c]];
            alo.x = fmaf(wl, f.x, alo.x);
            alo.y = fmaf(wl, f.y, alo.y);
            alo.z = fmaf(wl, f.z, alo.z);
            alo.w = fmaf(wl, f.w, alo.w);
            ahi.x = fmaf(wh, f.x, ahi.x);
            ahi.y = fmaf(wh, f.y, ahi.y);
            ahi.z = fmaf(wh, f.z, ahi.z);
            ahi.w = fmaf(wh, f.w, ahi.w);
        }

        if (full || (r0 + j < R)) {
            float4* o = reinterpret_cast<float4*>(out)
                        + ((size_t)(r0 + j) * 8 + w) * 64;
            o[lane]      = alo;
            o[32 + lane] = ahi;
        }

        // ring slot j&3 free after this point (reused by stage j+4 — never
        // issued before iteration j+2, so depth-2 is WAR-safe)
        asm volatile("" ::: "memory");

        bx0 = nx0; bx1 = nx1; bx2 = nx2;
        br0 = nr0; br1 = nr1; br2 = nr2;
    }
#undef GATHER
}

// ---------------------------------------------------------------------------
extern "C" void kernel_launch(void* const* d_in, const int* in_sizes, int n_in,
                              void* d_out, int out_size) {
    const float* inp     = (const float*)d_in[0];
    const int*   history = (const int*)d_in[1];
    const int*   depth   = (const int*)d_in[2];
    const float* nmin    = (const float*)d_in[3];
    const float* next    = (const float*)d_in[4];
    const float* emb     = (const float*)d_in[5];
    float*       out     = (float*)d_out;

    const int R = in_sizes[2];   // number of rays (= depth element count)

    depth_reduce_kernel<<<NRED, 256>>>(depth, R);
    nbvh_main_kernel<<<(R + NRAY - 1) / NRAY, 256>>>(
        inp, history, nmin, next, emb, out, R);
}